// round 3
// baseline (speedup 1.0000x reference)
#include <cuda_runtime.h>
#include <cuda_fp16.h>
#include <math.h>

#define BATCH 8
#define H 1024
#define W 1024
#define NWIN 5
#define PADY 64
#define ROWS (H + 2 * PADY)   // 1152 rows per (win,batch) image in scratch
#define NIMG (NWIN * BATCH)   // 40

__device__ __constant__ int c_radii[NWIN] = {3, 7, 15, 31, 63};

// Scratch: horizontal window sums (sum x, sum x^2) packed as half2, with
// PADY zero rows above and below each image so the vertical pass needs no
// bounds checks. 40 * 1152 * 1024 * 4B = 180 MiB.
// NOTE: pad rows are NEVER written by any kernel; __device__ globals are
// zero-initialized at module load, so they remain zero deterministically.
__device__ __half2 g_hsums[(size_t)NIMG * ROWS * W];

// ---------------------------------------------------------------------------
// Pass A: per-row inclusive prefix of (x, x^2) via warp shuffles + one block
// combine, then emit the 5 horizontal clipped-window sums as half2.
// One block per (row, batch). 1024 threads.
// ---------------------------------------------------------------------------
__global__ __launch_bounds__(1024) void hpass_kernel(const float* __restrict__ x,
                                                     __half2* __restrict__ hsums) {
    const int y = blockIdx.x;
    const int b = blockIdx.y;
    const int t = threadIdx.x;
    const int lane = t & 31;
    const int wid = t >> 5;

    __shared__ float2 s_warp[32];
    __shared__ float2 s_pref[W];

    const float v = x[((size_t)b * H + y) * W + t];
    float sx = v, sy = v * v;

    // warp-level inclusive scan
#pragma unroll
    for (int off = 1; off < 32; off <<= 1) {
        float ax = __shfl_up_sync(0xffffffffu, sx, off);
        float ay = __shfl_up_sync(0xffffffffu, sy, off);
        if (lane >= off) { sx += ax; sy += ay; }
    }
    if (lane == 31) s_warp[wid] = make_float2(sx, sy);
    __syncthreads();
    if (wid == 0) {
        float2 w2 = s_warp[lane];
        float wx = w2.x, wy = w2.y;
#pragma unroll
        for (int off = 1; off < 32; off <<= 1) {
            float ax = __shfl_up_sync(0xffffffffu, wx, off);
            float ay = __shfl_up_sync(0xffffffffu, wy, off);
            if (lane >= off) { wx += ax; wy += ay; }
        }
        s_warp[lane] = make_float2(wx, wy);
    }
    __syncthreads();
    if (wid > 0) {
        float2 base = s_warp[wid - 1];
        sx += base.x; sy += base.y;
    }
    s_pref[t] = make_float2(sx, sy);
    __syncthreads();

#pragma unroll
    for (int w = 0; w < NWIN; w++) {
        const int r = c_radii[w];
        const int lo = max(t - r, 0);
        const int hi = min(t + r, W - 1);
        float2 s = s_pref[hi];
        if (lo > 0) {
            float2 p = s_pref[lo - 1];
            s.x -= p.x; s.y -= p.y;
        }
        hsums[((size_t)(w * BATCH + b) * ROWS + PADY + y) * W + t] =
            __floats2half2_rn(s.x, s.y);
    }
}

// ---------------------------------------------------------------------------
// Pass B: vertical sliding window + Sauvola epilogue.
// One column per thread, 4B half2 loads (128B/warp-load), unroll 8 so the
// add/sub load streams batch (high MLP). No conditionals (pad rows are zero).
// grid.x = 4 xblocks * YCHUNKS, grid.y = BATCH, grid.z = NWIN; 256 threads.
// ---------------------------------------------------------------------------
#define XBLOCKS (W / 256)   // 4
#define YCHUNKS 8
#define YCHUNK (H / YCHUNKS)

__device__ __forceinline__ float2 h2f(unsigned int u) {
    __half2 h = *reinterpret_cast<__half2*>(&u);
    return __half22float2(h);
}

__global__ __launch_bounds__(256) void vpass_kernel(const __half2* __restrict__ hsums,
                                                    const float* __restrict__ kk,
                                                    const float* __restrict__ RR,
                                                    float* __restrict__ out) {
    const int xblk = blockIdx.x & (XBLOCKS - 1);
    const int ychunk = blockIdx.x / XBLOCKS;
    const int b = blockIdx.y;
    const int w = blockIdx.z;

    const int x = xblk * 256 + threadIdx.x;
    const int r = c_radii[w];
    const float kw = kk[w];
    const float invR = __frcp_rn(RR[w]);

    const unsigned int* col = reinterpret_cast<const unsigned int*>(
        hsums + ((size_t)(w * BATCH + b) * ROWS + PADY) * W) + x;
    float* o = out + (((size_t)b * NWIN + w) * H) * W + x;

    const float cnth = (float)(min(x + r, W - 1) - max(x - r, 0) + 1);

    const int y0 = ychunk * YCHUNK;

    float sx = 0.f, sy = 0.f;

    // Prime: S = sum of rows [y0-r, y0+r) (pad rows are zero, no clamping).
#pragma unroll 4
    for (int yy = y0 - r; yy < y0 + r; yy++) {
        float2 f = h2f(col[(size_t)yy * W]);
        sx += f.x; sy += f.y;
    }

#pragma unroll 8
    for (int y = y0; y < y0 + YCHUNK; y++) {
        // add row y+r (cached: will be re-read later as a subtract)
        float2 fa = h2f(col[(size_t)(y + r) * W]);
        // sub row y-r (dead after this: last-use hint)
        float2 fs = h2f(__ldlu(&col[(size_t)(y - r) * W]));

        sx += fa.x; sy += fa.y;

        const float cntv = (float)(min(y + r, H - 1) - max(y - r, 0) + 1);
        const float inv = __frcp_rn(cnth * cntv);
        const float mean = sx * inv;
        const float m2 = sy * inv;
        const float dev = sqrtf(fmaxf(fmaf(-mean, mean, m2), 1e-6f));
        // streaming store: output never re-read, keep L2 for hsums
        __stcs(o + (size_t)y * W, mean * fmaf(kw, fmaf(dev, invR, -1.0f), 1.0f));

        sx -= fs.x; sy -= fs.y;
    }
}

extern "C" void kernel_launch(void* const* d_in, const int* in_sizes, int n_in,
                              void* d_out, int out_size) {
    const float* x = (const float*)d_in[0];
    const float* k = (const float*)d_in[1];
    const float* R = (const float*)d_in[2];
    float* out = (float*)d_out;

    __half2* hsums;
    cudaGetSymbolAddress((void**)&hsums, g_hsums);

    dim3 gridA(H, BATCH);
    hpass_kernel<<<gridA, 1024>>>(x, hsums);

    dim3 gridB(XBLOCKS * YCHUNKS, BATCH, NWIN);
    vpass_kernel<<<gridB, 256>>>(hsums, k, R, out);
}